// round 1
// baseline (speedup 1.0000x reference)
#include <cuda_runtime.h>

namespace {

constexpr int HID  = 256;
constexpr int NOBJ = 20;
constexpr int NFD  = 16;
constexpr int NTHREADS = 256;
constexpr unsigned FULL_MASK = 0xFFFFFFFFu;

struct Params {
  const float* __restrict__ nf;   const int* __restrict__ nn_c;
  const float* __restrict__ neW;  const float* __restrict__ neb;
  const float* __restrict__ g1W1; const float* __restrict__ g1b1;
  const float* __restrict__ g1W2; const float* __restrict__ g1b2;
  const float* __restrict__ g2W1; const float* __restrict__ g2b1;
  const float* __restrict__ g2W2; const float* __restrict__ g2b2;
  const float* __restrict__ n1g;  const float* __restrict__ n1b;
  const float* __restrict__ n2g;  const float* __restrict__ n2b;
  const float* __restrict__ ohW;  const float* __restrict__ ohb;
  const float* __restrict__ c1W;  const float* __restrict__ c1b;
  const float* __restrict__ c2W;  const float* __restrict__ c2b;
  const float* __restrict__ pqW;  const float* __restrict__ pqb;
  const float* __restrict__ pkW;  const float* __restrict__ pkb;
  float* __restrict__ out;
  int B;
};

// Activations stored transposed: hT[feature k][row i], so GEMM reads are
// warp-broadcast LDS.128 (4 rows at a time) and per-thread column accumulators
// stay in registers.
struct Smem {
  alignas(16) float hT[HID * NOBJ];   // 20 KB
  alignas(16) float tT[HID * NOBJ];   // 20 KB
  float msgs[HID];                    // msg / g vector
  float nfs[NOBJ * NFD];              // raw node features
  float red[NOBJ][8][2];              // per-row, per-warp partials
  float stats[NOBJ][2];               // LN mean, rstd
};

__device__ __forceinline__ float warp_sum(float v) {
  v += __shfl_xor_sync(FULL_MASK, v, 16);
  v += __shfl_xor_sync(FULL_MASK, v, 8);
  v += __shfl_xor_sync(FULL_MASK, v, 4);
  v += __shfl_xor_sync(FULL_MASK, v, 2);
  v += __shfl_xor_sync(FULL_MASK, v, 1);
  return v;
}

// One message-passing block:
//   t  = relu(h @ W1[0:256] + msg @ W1[256:512] + b1)
//   h' = LN(h + t @ W2 + b2) * mask ;  msg' = masked_mean(h')
template <int NR>
__device__ __forceinline__ void layer(Smem& S, int j, int nc, float inv_denom,
                                      const float* __restrict__ W1,
                                      const float* __restrict__ b1,
                                      const float* __restrict__ W2,
                                      const float* __restrict__ b2,
                                      const float* __restrict__ lg,
                                      const float* __restrict__ lb,
                                      int lane, int warp) {
  // ---- msg part of W1 (identical for all rows) ----
  float m0 = b1[j], m1 = 0.f, m2 = 0.f, m3 = 0.f;
  {
    const float* w1b = W1 + HID * HID + j;
    #pragma unroll 2
    for (int k = 0; k < HID; k += 4) {
      m0 = fmaf(S.msgs[k + 0], w1b[(k + 0) * HID], m0);
      m1 = fmaf(S.msgs[k + 1], w1b[(k + 1) * HID], m1);
      m2 = fmaf(S.msgs[k + 2], w1b[(k + 2) * HID], m2);
      m3 = fmaf(S.msgs[k + 3], w1b[(k + 3) * HID], m3);
    }
  }
  const float mterm = (m0 + m1) + (m2 + m3);

  // ---- t = relu(h @ W1a + mterm) ----
  float t[NR];
  #pragma unroll
  for (int i = 0; i < NR; i++) t[i] = mterm;
  {
    const float* w1a = W1 + j;
    #pragma unroll 4
    for (int k = 0; k < HID; k++) {
      const float w = w1a[k * HID];
      const float4* hv = reinterpret_cast<const float4*>(&S.hT[k * NOBJ]);
      #pragma unroll
      for (int r = 0; r < NR / 4; r++) {
        float4 v = hv[r];
        t[4 * r + 0] = fmaf(v.x, w, t[4 * r + 0]);
        t[4 * r + 1] = fmaf(v.y, w, t[4 * r + 1]);
        t[4 * r + 2] = fmaf(v.z, w, t[4 * r + 2]);
        t[4 * r + 3] = fmaf(v.w, w, t[4 * r + 3]);
      }
    }
  }
  #pragma unroll
  for (int i = 0; i < NR; i++) {
    t[i] = fmaxf(t[i], 0.f);
    S.tT[j * NOBJ + i] = t[i];
  }
  __syncthreads();

  // ---- hn = h_old + t @ W2 + b2 ----
  float hn[NR];
  {
    const float bb = b2[j];
    #pragma unroll
    for (int i = 0; i < NR; i++) hn[i] = bb + S.hT[j * NOBJ + i];
    const float* w2 = W2 + j;
    #pragma unroll 4
    for (int k = 0; k < HID; k++) {
      const float w = w2[k * HID];
      const float4* tv = reinterpret_cast<const float4*>(&S.tT[k * NOBJ]);
      #pragma unroll
      for (int r = 0; r < NR / 4; r++) {
        float4 v = tv[r];
        hn[4 * r + 0] = fmaf(v.x, w, hn[4 * r + 0]);
        hn[4 * r + 1] = fmaf(v.y, w, hn[4 * r + 1]);
        hn[4 * r + 2] = fmaf(v.z, w, hn[4 * r + 2]);
        hn[4 * r + 3] = fmaf(v.w, w, hn[4 * r + 3]);
      }
    }
  }

  // ---- LayerNorm stats: block-wide sum / sumsq per row ----
  #pragma unroll
  for (int i = 0; i < NR; i++) {
    float s = warp_sum(hn[i]);
    float q = warp_sum(hn[i] * hn[i]);
    if (lane == 0) { S.red[i][warp][0] = s; S.red[i][warp][1] = q; }
  }
  __syncthreads();
  if (j < NR) {
    float s = 0.f, q = 0.f;
    #pragma unroll
    for (int w = 0; w < 8; w++) { s += S.red[j][w][0]; q += S.red[j][w][1]; }
    const float mean = s * (1.0f / HID);
    const float var  = q * (1.0f / HID) - mean * mean;
    S.stats[j][0] = mean;
    S.stats[j][1] = rsqrtf(var + 1e-5f);
  }
  __syncthreads();

  // ---- normalize, mask, write back, new msg ----
  const float gw = lg[j], gb = lb[j];
  float ms = 0.f;
  #pragma unroll
  for (int i = 0; i < NR; i++) {
    float v = 0.f;
    if (i < nc) v = (hn[i] - S.stats[i][0]) * S.stats[i][1] * gw + gb;
    S.hT[j * NOBJ + i] = v;
    ms += v;
  }
  S.msgs[j] = ms * inv_denom;
  __syncthreads();
}

template <int NR>
__device__ __forceinline__ void run(const Params& P, Smem& S, int b, int nc,
                                    int tid) {
  const int lane = tid & 31;
  const int warp = tid >> 5;
  const float inv_denom = 1.0f / (float)(nc > 0 ? nc : 1);

  for (int idx = tid; idx < NOBJ * NFD; idx += NTHREADS)
    S.nfs[idx] = P.nf[b * (NOBJ * NFD) + idx];
  __syncthreads();

  const int j = tid;

  // ---- node embed: h0 = nf @ neW + neb ----
  {
    float acc[NR];
    const float bias = P.neb[j];
    #pragma unroll
    for (int i = 0; i < NR; i++) acc[i] = bias;
    #pragma unroll
    for (int k = 0; k < NFD; k++) {
      const float w = P.neW[k * HID + j];
      #pragma unroll
      for (int i = 0; i < NR; i++)
        acc[i] = fmaf(S.nfs[i * NFD + k], w, acc[i]);
    }
    float ms = 0.f;
    #pragma unroll
    for (int i = 0; i < NR; i++) {
      S.hT[j * NOBJ + i] = acc[i];
      if (i < nc) ms += acc[i];
    }
    S.msgs[j] = ms * inv_denom;
  }
  __syncthreads();

  layer<NR>(S, j, nc, inv_denom, P.g1W1, P.g1b1, P.g1W2, P.g1b2, P.n1g, P.n1b,
            lane, warp);
  layer<NR>(S, j, nc, inv_denom, P.g2W1, P.g2b1, P.g2W2, P.g2b2, P.n2g, P.n2b,
            lane, warp);
  // now: S.msgs == g (graph readout), S.hT == final h

  // ---- q = g @ pqW + pqb ----
  float q0 = P.pqb[j], q1 = 0.f, q2 = 0.f, q3 = 0.f;
  {
    const float* wq = P.pqW + j;
    #pragma unroll 2
    for (int k = 0; k < HID; k += 4) {
      q0 = fmaf(S.msgs[k + 0], wq[(k + 0) * HID], q0);
      q1 = fmaf(S.msgs[k + 1], wq[(k + 1) * HID], q1);
      q2 = fmaf(S.msgs[k + 2], wq[(k + 2) * HID], q2);
      q3 = fmaf(S.msgs[k + 3], wq[(k + 3) * HID], q3);
    }
  }
  const float qj = (q0 + q1) + (q2 + q3);

  // ---- k = h @ pkW + pkb ; pl[i] = sum_j q[j] * k[i][j] ----
  float kk[NR];
  {
    const float pb = P.pkb[j];
    #pragma unroll
    for (int i = 0; i < NR; i++) kk[i] = pb;
    const float* wk = P.pkW + j;
    #pragma unroll 4
    for (int k = 0; k < HID; k++) {
      const float w = wk[k * HID];
      const float4* hv = reinterpret_cast<const float4*>(&S.hT[k * NOBJ]);
      #pragma unroll
      for (int r = 0; r < NR / 4; r++) {
        float4 v = hv[r];
        kk[4 * r + 0] = fmaf(v.x, w, kk[4 * r + 0]);
        kk[4 * r + 1] = fmaf(v.y, w, kk[4 * r + 1]);
        kk[4 * r + 2] = fmaf(v.z, w, kk[4 * r + 2]);
        kk[4 * r + 3] = fmaf(v.w, w, kk[4 * r + 3]);
      }
    }
  }
  #pragma unroll
  for (int i = 0; i < NR; i++) {
    float s = warp_sum(qj * kk[i]);
    if (lane == 0) S.red[i][warp][0] = s;
  }
  __syncthreads();

  // ---- pl output (all 20 slots; masked -> -1e9) ----
  if (tid < NOBJ) {
    float pl = -1e9f;
    if (tid < nc) {
      float s = 0.f;
      #pragma unroll
      for (int w = 0; w < 8; w++) s += S.red[tid][w][0];
      pl = s;
    }
    P.out[(size_t)P.B * 28 + (size_t)b * NOBJ + tid] = pl;
  }

  // ---- heads: oh (8), c1 (10), c2 (10) from g, spread over 3 warps ----
  if (tid < 8) {
    const int c = tid;
    float a0 = P.ohb[c], a1 = 0.f, a2 = 0.f, a3 = 0.f;
    #pragma unroll 2
    for (int k = 0; k < HID; k += 4) {
      a0 = fmaf(S.msgs[k + 0], P.ohW[(k + 0) * 8 + c], a0);
      a1 = fmaf(S.msgs[k + 1], P.ohW[(k + 1) * 8 + c], a1);
      a2 = fmaf(S.msgs[k + 2], P.ohW[(k + 2) * 8 + c], a2);
      a3 = fmaf(S.msgs[k + 3], P.ohW[(k + 3) * 8 + c], a3);
    }
    P.out[(size_t)b * 8 + c] = (a0 + a1) + (a2 + a3);
  } else if (tid >= 32 && tid < 42) {
    const int c = tid - 32;
    float a0 = P.c1b[c], a1 = 0.f, a2 = 0.f, a3 = 0.f;
    #pragma unroll 2
    for (int k = 0; k < HID; k += 4) {
      a0 = fmaf(S.msgs[k + 0], P.c1W[(k + 0) * 10 + c], a0);
      a1 = fmaf(S.msgs[k + 1], P.c1W[(k + 1) * 10 + c], a1);
      a2 = fmaf(S.msgs[k + 2], P.c1W[(k + 2) * 10 + c], a2);
      a3 = fmaf(S.msgs[k + 3], P.c1W[(k + 3) * 10 + c], a3);
    }
    P.out[(size_t)P.B * 8 + (size_t)b * 10 + c] = (a0 + a1) + (a2 + a3);
  } else if (tid >= 64 && tid < 74) {
    const int c = tid - 64;
    float a0 = P.c2b[c], a1 = 0.f, a2 = 0.f, a3 = 0.f;
    #pragma unroll 2
    for (int k = 0; k < HID; k += 4) {
      a0 = fmaf(S.msgs[k + 0], P.c2W[(k + 0) * 10 + c], a0);
      a1 = fmaf(S.msgs[k + 1], P.c2W[(k + 1) * 10 + c], a1);
      a2 = fmaf(S.msgs[k + 2], P.c2W[(k + 2) * 10 + c], a2);
      a3 = fmaf(S.msgs[k + 3], P.c2W[(k + 3) * 10 + c], a3);
    }
    P.out[(size_t)P.B * 18 + (size_t)b * 10 + c] = (a0 + a1) + (a2 + a3);
  }
}

__global__ void __launch_bounds__(NTHREADS, 2) gnn_kernel(Params P) {
  __shared__ Smem S;
  const int b = blockIdx.x;
  int nc = P.nn_c[b];
  nc = min(max(nc, 0), NOBJ);
  // Round valid-row count up to a multiple of 4; nc is uniform per block so
  // the divergent-looking switch (and the __syncthreads inside) is uniform.
  const int g = ((nc > 0 ? nc : 1) + 3) >> 2;
  switch (g) {
    case 1:  run<4>(P, S, b, nc, threadIdx.x);  break;
    case 2:  run<8>(P, S, b, nc, threadIdx.x);  break;
    case 3:  run<12>(P, S, b, nc, threadIdx.x); break;
    case 4:  run<16>(P, S, b, nc, threadIdx.x); break;
    default: run<20>(P, S, b, nc, threadIdx.x); break;
  }
}

}  // namespace

extern "C" void kernel_launch(void* const* d_in, const int* in_sizes, int n_in,
                              void* d_out, int out_size) {
  Params P;
  P.nf   = (const float*)d_in[0];
  P.nn_c = (const int*)d_in[1];
  P.neW  = (const float*)d_in[2];  P.neb  = (const float*)d_in[3];
  P.g1W1 = (const float*)d_in[4];  P.g1b1 = (const float*)d_in[5];
  P.g1W2 = (const float*)d_in[6];  P.g1b2 = (const float*)d_in[7];
  P.g2W1 = (const float*)d_in[8];  P.g2b1 = (const float*)d_in[9];
  P.g2W2 = (const float*)d_in[10]; P.g2b2 = (const float*)d_in[11];
  P.n1g  = (const float*)d_in[12]; P.n1b  = (const float*)d_in[13];
  P.n2g  = (const float*)d_in[14]; P.n2b  = (const float*)d_in[15];
  P.ohW  = (const float*)d_in[16]; P.ohb  = (const float*)d_in[17];
  P.c1W  = (const float*)d_in[18]; P.c1b  = (const float*)d_in[19];
  P.c2W  = (const float*)d_in[20]; P.c2b  = (const float*)d_in[21];
  P.pqW  = (const float*)d_in[22]; P.pqb  = (const float*)d_in[23];
  P.pkW  = (const float*)d_in[24]; P.pkb  = (const float*)d_in[25];
  P.out  = (float*)d_out;
  P.B    = in_sizes[1];

  gnn_kernel<<<P.B, NTHREADS>>>(P);
}

// round 2
// speedup vs baseline: 1.1323x; 1.1323x over previous
#include <cuda_runtime.h>

namespace {

constexpr int HID  = 256;
constexpr int NOBJ = 20;
constexpr int NFD  = 16;
constexpr int NT   = 256;   // threads per block
constexpr int G    = 4;     // samples per CTA
constexpr int KT   = 32;    // weight k-tile rows
constexpr int MAXB = 16384;
constexpr unsigned FULL_MASK = 0xFFFFFFFFu;

__device__ int d_perm[MAXB];

struct Params {
  const float* __restrict__ nf;   const int* __restrict__ nn_c;
  const float* __restrict__ neW;  const float* __restrict__ neb;
  const float* __restrict__ g1W1; const float* __restrict__ g1b1;
  const float* __restrict__ g1W2; const float* __restrict__ g1b2;
  const float* __restrict__ g2W1; const float* __restrict__ g2b1;
  const float* __restrict__ g2W2; const float* __restrict__ g2b2;
  const float* __restrict__ n1g;  const float* __restrict__ n1b;
  const float* __restrict__ n2g;  const float* __restrict__ n2b;
  const float* __restrict__ ohW;  const float* __restrict__ ohb;
  const float* __restrict__ c1W;  const float* __restrict__ c1b;
  const float* __restrict__ c2W;  const float* __restrict__ c2b;
  const float* __restrict__ pqW;  const float* __restrict__ pqb;
  const float* __restrict__ pkW;  const float* __restrict__ pkb;
  float* __restrict__ out;
  int B;
};

__device__ __forceinline__ void cp_async16(void* smem, const void* gmem) {
  unsigned s = (unsigned)__cvta_generic_to_shared(smem);
  asm volatile("cp.async.cg.shared.global [%0], [%1], 16;\n" ::"r"(s), "l"(gmem));
}
__device__ __forceinline__ void cp_commit() {
  asm volatile("cp.async.commit_group;\n");
}
__device__ __forceinline__ void cp_wait1() {
  asm volatile("cp.async.wait_group 1;\n");
}

__device__ __forceinline__ float warp_sum(float v) {
  v += __shfl_xor_sync(FULL_MASK, v, 16);
  v += __shfl_xor_sync(FULL_MASK, v, 8);
  v += __shfl_xor_sync(FULL_MASK, v, 4);
  v += __shfl_xor_sync(FULL_MASK, v, 2);
  v += __shfl_xor_sync(FULL_MASK, v, 1);
  return v;
}

// Cooperative load of one KT x HID weight tile into smem via cp.async.
__device__ __forceinline__ void load_tile(float* dst, const float* W, int k0,
                                          int tid) {
  const float4* src = reinterpret_cast<const float4*>(W + (size_t)k0 * HID);
  float4* d = reinterpret_cast<float4*>(dst);
  constexpr int V = KT * HID / 4;  // 2048 float4
  #pragma unroll
  for (int r = 0; r < V / NT; r++)
    cp_async16(&d[tid + r * NT], &src[tid + r * NT]);
}

// ------------------------------------------------------------------
// One message-passing layer for G samples, NR row-slots per sample.
// hT layout: hT[k*ROWS + g*NR + i]  (feature-major, rows inner)
// ------------------------------------------------------------------
template <int NR>
__device__ __forceinline__ void layer(float* hT, float* wbuf, float* msgs,
                                      float* red, float* stats,
                                      const int* ncv, const float* invd,
                                      const float* __restrict__ W1,
                                      const float* __restrict__ b1,
                                      const float* __restrict__ W2,
                                      const float* __restrict__ b2,
                                      const float* __restrict__ lg,
                                      const float* __restrict__ lb,
                                      int tid, int lane, int warp) {
  constexpr int ROWS = G * NR;
  const int j = tid;

  // ---------- t = relu([h | msg] @ W1 + b1) ----------
  float t[G][NR];
  float mac[G];
  #pragma unroll
  for (int g = 0; g < G; g++) {
    mac[g] = 0.f;
    #pragma unroll
    for (int i = 0; i < NR; i++) t[g][i] = 0.f;
  }

  constexpr int NT1 = 512 / KT;  // 16 tiles (first 8 = h-part, rest = msg)
  load_tile(wbuf, W1, 0, tid);
  cp_commit();
  for (int tt = 0; tt < NT1; tt++) {
    if (tt + 1 < NT1) load_tile(wbuf + ((tt + 1) & 1) * KT * HID, W1, (tt + 1) * KT, tid);
    cp_commit();
    cp_wait1();
    __syncthreads();
    const float* wb = wbuf + (tt & 1) * KT * HID;
    const int k0 = tt * KT;
    if (k0 < HID) {
      #pragma unroll 2
      for (int kk = 0; kk < KT; kk++) {
        const float w = wb[kk * HID + j];
        const float4* hv = reinterpret_cast<const float4*>(hT + (size_t)(k0 + kk) * ROWS);
        #pragma unroll
        for (int g = 0; g < G; g++) {
          #pragma unroll
          for (int r = 0; r < NR / 4; r++) {
            float4 v = hv[g * (NR / 4) + r];
            t[g][4 * r + 0] = fmaf(v.x, w, t[g][4 * r + 0]);
            t[g][4 * r + 1] = fmaf(v.y, w, t[g][4 * r + 1]);
            t[g][4 * r + 2] = fmaf(v.z, w, t[g][4 * r + 2]);
            t[g][4 * r + 3] = fmaf(v.w, w, t[g][4 * r + 3]);
          }
        }
      }
    } else {
      #pragma unroll 8
      for (int kk = 0; kk < KT; kk++) {
        const float w = wb[kk * HID + j];
        const int km = k0 + kk - HID;
        #pragma unroll
        for (int g = 0; g < G; g++)
          mac[g] = fmaf(msgs[g * HID + km], w, mac[g]);
      }
    }
    __syncthreads();
  }

  // residual init (row-local: thread j owns feature j of every row)
  float hn[G][NR];
  {
    const float bb = b2[j];
    #pragma unroll
    for (int g = 0; g < G; g++)
      #pragma unroll
      for (int i = 0; i < NR; i++)
        hn[g][i] = bb + hT[(size_t)j * ROWS + g * NR + i];
  }
  // overwrite hT with relu(t + mac + b1)
  {
    const float b1j = b1[j];
    #pragma unroll
    for (int g = 0; g < G; g++) {
      const float m = mac[g] + b1j;
      #pragma unroll
      for (int i = 0; i < NR; i++)
        hT[(size_t)j * ROWS + g * NR + i] = fmaxf(t[g][i] + m, 0.f);
    }
  }
  __syncthreads();

  // ---------- hn += t @ W2 ----------
  constexpr int NT2 = HID / KT;  // 8 tiles
  load_tile(wbuf, W2, 0, tid);
  cp_commit();
  for (int tt = 0; tt < NT2; tt++) {
    if (tt + 1 < NT2) load_tile(wbuf + ((tt + 1) & 1) * KT * HID, W2, (tt + 1) * KT, tid);
    cp_commit();
    cp_wait1();
    __syncthreads();
    const float* wb = wbuf + (tt & 1) * KT * HID;
    const int k0 = tt * KT;
    #pragma unroll 2
    for (int kk = 0; kk < KT; kk++) {
      const float w = wb[kk * HID + j];
      const float4* tv = reinterpret_cast<const float4*>(hT + (size_t)(k0 + kk) * ROWS);
      #pragma unroll
      for (int g = 0; g < G; g++) {
        #pragma unroll
        for (int r = 0; r < NR / 4; r++) {
          float4 v = tv[g * (NR / 4) + r];
          hn[g][4 * r + 0] = fmaf(v.x, w, hn[g][4 * r + 0]);
          hn[g][4 * r + 1] = fmaf(v.y, w, hn[g][4 * r + 1]);
          hn[g][4 * r + 2] = fmaf(v.z, w, hn[g][4 * r + 2]);
          hn[g][4 * r + 3] = fmaf(v.w, w, hn[g][4 * r + 3]);
        }
      }
    }
    __syncthreads();
  }

  // ---------- LayerNorm stats ----------
  #pragma unroll
  for (int g = 0; g < G; g++) {
    #pragma unroll
    for (int i = 0; i < NR; i++) {
      float s = warp_sum(hn[g][i]);
      float q = warp_sum(hn[g][i] * hn[g][i]);
      if (lane == 0) {
        red[((g * NR + i) * 8 + warp) * 2 + 0] = s;
        red[((g * NR + i) * 8 + warp) * 2 + 1] = q;
      }
    }
  }
  __syncthreads();
  if (tid < G * NR) {
    float s = 0.f, q = 0.f;
    #pragma unroll
    for (int w = 0; w < 8; w++) {
      s += red[(tid * 8 + w) * 2 + 0];
      q += red[(tid * 8 + w) * 2 + 1];
    }
    const float mean = s * (1.0f / HID);
    const float var  = q * (1.0f / HID) - mean * mean;
    stats[tid * 2 + 0] = mean;
    stats[tid * 2 + 1] = rsqrtf(var + 1e-5f);
  }
  __syncthreads();

  // ---------- normalize, mask, write back, new msg ----------
  const float gw = lg[j], gb = lb[j];
  #pragma unroll
  for (int g = 0; g < G; g++) {
    float ms = 0.f;
    #pragma unroll
    for (int i = 0; i < NR; i++) {
      float v = 0.f;
      if (i < ncv[g])
        v = (hn[g][i] - stats[(g * NR + i) * 2]) * stats[(g * NR + i) * 2 + 1] * gw + gb;
      hT[(size_t)j * ROWS + g * NR + i] = v;
      ms += v;
    }
    msgs[g * HID + j] = ms * invd[g];
  }
  __syncthreads();
}

template <int NR>
__device__ __forceinline__ void run(const Params& P, float* sm, int c, int tid) {
  constexpr int ROWS = G * NR;
  float* hT    = sm;                       // 256*ROWS
  float* wbuf  = hT + HID * ROWS;          // 2*KT*256
  float* msgs  = wbuf + 2 * KT * HID;      // G*256
  float* nfs   = msgs + G * HID;           // G*320
  float* red   = nfs + G * NOBJ * NFD;     // G*NR*16
  float* stats = red + G * NR * 16;        // G*NR*2

  const int lane = tid & 31, warp = tid >> 5, j = tid;

  int   sid[G]; int ncv[G]; float invd[G]; bool wok[G];
  #pragma unroll
  for (int g = 0; g < G; g++) {
    const int s = c * G + g;
    wok[g] = (s < P.B);
    sid[g] = wok[g] ? d_perm[s] : 0;
    int nc = wok[g] ? P.nn_c[sid[g]] : 0;
    ncv[g] = min(max(nc, 0), NOBJ);
    invd[g] = 1.0f / (float)(ncv[g] > 0 ? ncv[g] : 1);
  }

  // load node features (G*320 floats = G*80 float4)
  for (int idx = tid; idx < G * 80; idx += NT) {
    const int g = idx / 80, o = idx % 80;
    reinterpret_cast<float4*>(nfs)[idx] =
        reinterpret_cast<const float4*>(P.nf + (size_t)sid[g] * (NOBJ * NFD))[o];
  }
  __syncthreads();

  // ---------- node embed ----------
  {
    float wv[NFD];
    #pragma unroll
    for (int k = 0; k < NFD; k++) wv[k] = P.neW[k * HID + j];
    const float bias = P.neb[j];
    #pragma unroll
    for (int g = 0; g < G; g++) {
      float ms = 0.f;
      #pragma unroll
      for (int i = 0; i < NR; i++) {
        const float4* rp = reinterpret_cast<const float4*>(nfs + g * 320 + i * NFD);
        float4 r0 = rp[0], r1 = rp[1], r2 = rp[2], r3 = rp[3];
        float a = bias;
        a = fmaf(r0.x, wv[0], a);  a = fmaf(r0.y, wv[1], a);
        a = fmaf(r0.z, wv[2], a);  a = fmaf(r0.w, wv[3], a);
        a = fmaf(r1.x, wv[4], a);  a = fmaf(r1.y, wv[5], a);
        a = fmaf(r1.z, wv[6], a);  a = fmaf(r1.w, wv[7], a);
        a = fmaf(r2.x, wv[8], a);  a = fmaf(r2.y, wv[9], a);
        a = fmaf(r2.z, wv[10], a); a = fmaf(r2.w, wv[11], a);
        a = fmaf(r3.x, wv[12], a); a = fmaf(r3.y, wv[13], a);
        a = fmaf(r3.z, wv[14], a); a = fmaf(r3.w, wv[15], a);
        hT[(size_t)j * ROWS + g * NR + i] = a;
        if (i < ncv[g]) ms += a;
      }
      msgs[g * HID + j] = ms * invd[g];
    }
  }
  __syncthreads();

  layer<NR>(hT, wbuf, msgs, red, stats, ncv, invd,
            P.g1W1, P.g1b1, P.g1W2, P.g1b2, P.n1g, P.n1b, tid, lane, warp);
  layer<NR>(hT, wbuf, msgs, red, stats, ncv, invd,
            P.g2W1, P.g2b1, P.g2W2, P.g2b2, P.n2g, P.n2b, tid, lane, warp);
  // msgs == per-sample g vector, hT == final h

  // ---------- q = g @ pqW + pqb (tiled) ----------
  float qv[G];
  {
    const float qb = P.pqb[j];
    #pragma unroll
    for (int g = 0; g < G; g++) qv[g] = qb;
    constexpr int NTq = HID / KT;
    load_tile(wbuf, P.pqW, 0, tid);
    cp_commit();
    for (int tt = 0; tt < NTq; tt++) {
      if (tt + 1 < NTq) load_tile(wbuf + ((tt + 1) & 1) * KT * HID, P.pqW, (tt + 1) * KT, tid);
      cp_commit();
      cp_wait1();
      __syncthreads();
      const float* wb = wbuf + (tt & 1) * KT * HID;
      const int k0 = tt * KT;
      #pragma unroll 8
      for (int kk = 0; kk < KT; kk++) {
        const float w = wb[kk * HID + j];
        #pragma unroll
        for (int g = 0; g < G; g++)
          qv[g] = fmaf(msgs[g * HID + k0 + kk], w, qv[g]);
      }
      __syncthreads();
    }
  }

  // ---------- k = h @ pkW + pkb ; pl = q . k ----------
  float kk_[G][NR];
  {
    const float pb = P.pkb[j];
    #pragma unroll
    for (int g = 0; g < G; g++)
      #pragma unroll
      for (int i = 0; i < NR; i++) kk_[g][i] = pb;
    constexpr int NTk = HID / KT;
    load_tile(wbuf, P.pkW, 0, tid);
    cp_commit();
    for (int tt = 0; tt < NTk; tt++) {
      if (tt + 1 < NTk) load_tile(wbuf + ((tt + 1) & 1) * KT * HID, P.pkW, (tt + 1) * KT, tid);
      cp_commit();
      cp_wait1();
      __syncthreads();
      const float* wb = wbuf + (tt & 1) * KT * HID;
      const int k0 = tt * KT;
      #pragma unroll 2
      for (int kkx = 0; kkx < KT; kkx++) {
        const float w = wb[kkx * HID + j];
        const float4* hv = reinterpret_cast<const float4*>(hT + (size_t)(k0 + kkx) * ROWS);
        #pragma unroll
        for (int g = 0; g < G; g++) {
          #pragma unroll
          for (int r = 0; r < NR / 4; r++) {
            float4 v = hv[g * (NR / 4) + r];
            kk_[g][4 * r + 0] = fmaf(v.x, w, kk_[g][4 * r + 0]);
            kk_[g][4 * r + 1] = fmaf(v.y, w, kk_[g][4 * r + 1]);
            kk_[g][4 * r + 2] = fmaf(v.z, w, kk_[g][4 * r + 2]);
            kk_[g][4 * r + 3] = fmaf(v.w, w, kk_[g][4 * r + 3]);
          }
        }
      }
      __syncthreads();
    }
  }
  #pragma unroll
  for (int g = 0; g < G; g++) {
    #pragma unroll
    for (int i = 0; i < NR; i++) {
      float s = warp_sum(qv[g] * kk_[g][i]);
      if (lane == 0) red[((g * NR + i) * 8 + warp) * 2] = s;
    }
  }
  __syncthreads();

  // ---------- pl output (all 20 slots) ----------
  if (tid < G * NOBJ) {
    const int g = tid / NOBJ, i = tid % NOBJ;
    if (wok[g]) {
      float v = -1e9f;
      if (i < ncv[g]) {
        float s = 0.f;
        #pragma unroll
        for (int w = 0; w < 8; w++) s += red[((g * NR + i) * 8 + w) * 2];
        v = s;
      }
      P.out[(size_t)P.B * 28 + (size_t)sid[g] * NOBJ + i] = v;
    }
  }

  // ---------- small heads from g-vector ----------
  if (tid < G * 28) {
    const int g = tid / 28;
    int cc = tid % 28;
    if (wok[g]) {
      const float* W; float bb; float* o; int no;
      if (cc < 8)       { W = P.ohW;  bb = P.ohb[cc];      no = 8;
                          o = P.out + (size_t)sid[g] * 8 + cc; }
      else if (cc < 18) { cc -= 8;  W = P.c1W; bb = P.c1b[cc]; no = 10;
                          o = P.out + (size_t)P.B * 8 + (size_t)sid[g] * 10 + cc; }
      else              { cc -= 18; W = P.c2W; bb = P.c2b[cc]; no = 10;
                          o = P.out + (size_t)P.B * 18 + (size_t)sid[g] * 10 + cc; }
      float a0 = bb, a1 = 0.f, a2 = 0.f, a3 = 0.f;
      const float* mg = msgs + g * HID;
      #pragma unroll 2
      for (int k = 0; k < HID; k += 4) {
        a0 = fmaf(mg[k + 0], W[(k + 0) * no + cc], a0);
        a1 = fmaf(mg[k + 1], W[(k + 1) * no + cc], a1);
        a2 = fmaf(mg[k + 2], W[(k + 2) * no + cc], a2);
        a3 = fmaf(mg[k + 3], W[(k + 3) * no + cc], a3);
      }
      *o = (a0 + a1) + (a2 + a3);
    }
  }
}

__global__ void __launch_bounds__(1024, 1) pack_kernel(const int* __restrict__ nn_c, int B) {
  __shared__ int cnt[5], base[5];
  const int tid = threadIdx.x;
  if (tid < 5) cnt[tid] = 0;
  __syncthreads();
  for (int i = tid; i < B; i += 1024) {
    int nc = min(max(nn_c[i], 0), NOBJ);
    int g = ((nc > 0 ? nc : 1) + 3) >> 2;  // 1..5
    atomicAdd(&cnt[g - 1], 1);
  }
  __syncthreads();
  if (tid == 0) {
    int s = 0;
    for (int g = 0; g < 5; g++) { base[g] = s; s += cnt[g]; }
  }
  __syncthreads();
  if (tid < 5) cnt[tid] = 0;
  __syncthreads();
  for (int i = tid; i < B; i += 1024) {
    int nc = min(max(nn_c[i], 0), NOBJ);
    int g = ((nc > 0 ? nc : 1) + 3) >> 2;
    int slot = base[g - 1] + atomicAdd(&cnt[g - 1], 1);
    d_perm[slot] = i;
  }
}

__global__ void __launch_bounds__(NT, 1) gnn_kernel(Params P) {
  extern __shared__ __align__(16) float sm[];
  const int c = blockIdx.x;
  // CTA bucket = max over its G samples
  int gmax = 1;
  #pragma unroll
  for (int g = 0; g < G; g++) {
    const int s = c * G + g;
    if (s < P.B) {
      int nc = min(max(P.nn_c[d_perm[s]], 0), NOBJ);
      int gg = ((nc > 0 ? nc : 1) + 3) >> 2;
      gmax = max(gmax, gg);
    }
  }
  switch (gmax) {
    case 1:  run<4>(P, sm, c, threadIdx.x);  break;
    case 2:  run<8>(P, sm, c, threadIdx.x);  break;
    case 3:  run<12>(P, sm, c, threadIdx.x); break;
    case 4:  run<16>(P, sm, c, threadIdx.x); break;
    default: run<20>(P, sm, c, threadIdx.x); break;
  }
}

constexpr int SMEM_FLOATS =
    HID * (G * 20) + 2 * KT * HID + G * HID + G * NOBJ * NFD + G * 20 * 16 + G * 20 * 2;
constexpr int SMEM_BYTES = SMEM_FLOATS * 4;  // 162,432 B

}  // namespace

extern "C" void kernel_launch(void* const* d_in, const int* in_sizes, int n_in,
                              void* d_out, int out_size) {
  Params P;
  P.nf   = (const float*)d_in[0];
  P.nn_c = (const int*)d_in[1];
  P.neW  = (const float*)d_in[2];  P.neb  = (const float*)d_in[3];
  P.g1W1 = (const float*)d_in[4];  P.g1b1 = (const float*)d_in[5];
  P.g1W2 = (const float*)d_in[6];  P.g1b2 = (const float*)d_in[7];
  P.g2W1 = (const float*)d_in[8];  P.g2b1 = (const float*)d_in[9];
  P.g2W2 = (const float*)d_in[10]; P.g2b2 = (const float*)d_in[11];
  P.n1g  = (const float*)d_in[12]; P.n1b  = (const float*)d_in[13];
  P.n2g  = (const float*)d_in[14]; P.n2b  = (const float*)d_in[15];
  P.ohW  = (const float*)d_in[16]; P.ohb  = (const float*)d_in[17];
  P.c1W  = (const float*)d_in[18]; P.c1b  = (const float*)d_in[19];
  P.c2W  = (const float*)d_in[20]; P.c2b  = (const float*)d_in[21];
  P.pqW  = (const float*)d_in[22]; P.pqb  = (const float*)d_in[23];
  P.pkW  = (const float*)d_in[24]; P.pkb  = (const float*)d_in[25];
  P.out  = (float*)d_out;
  P.B    = in_sizes[1];

  cudaFuncSetAttribute(gnn_kernel, cudaFuncAttributeMaxDynamicSharedMemorySize,
                       SMEM_BYTES);

  pack_kernel<<<1, 1024>>>(P.nn_c, P.B);
  const int nblocks = (P.B + G - 1) / G;
  gnn_kernel<<<nblocks, NT, SMEM_BYTES>>>(P);
}

// round 5
// speedup vs baseline: 1.2550x; 1.1084x over previous
#include <cuda_runtime.h>

namespace {

constexpr int HID  = 256;
constexpr int NOBJ = 20;
constexpr int NFD  = 16;
constexpr int NT   = 256;     // threads per block
constexpr int KT   = 16;      // weight k-tile rows
constexpr int TILE_F = KT * HID;  // floats per tile (4096)
constexpr int MAXB = 16384;
constexpr unsigned FULL_MASK = 0xFFFFFFFFu;

using u64 = unsigned long long;

__device__ int d_perm[MAXB];

struct Params {
  const float* __restrict__ nf;   const int* __restrict__ nn_c;
  const float* __restrict__ neW;  const float* __restrict__ neb;
  const float* __restrict__ g1W1; const float* __restrict__ g1b1;
  const float* __restrict__ g1W2; const float* __restrict__ g1b2;
  const float* __restrict__ g2W1; const float* __restrict__ g2b1;
  const float* __restrict__ g2W2; const float* __restrict__ g2b2;
  const float* __restrict__ n1g;  const float* __restrict__ n1b;
  const float* __restrict__ n2g;  const float* __restrict__ n2b;
  const float* __restrict__ ohW;  const float* __restrict__ ohb;
  const float* __restrict__ c1W;  const float* __restrict__ c1b;
  const float* __restrict__ c2W;  const float* __restrict__ c2b;
  const float* __restrict__ pqW;  const float* __restrict__ pqb;
  const float* __restrict__ pkW;  const float* __restrict__ pkb;
  float* __restrict__ out;
  int B;
};

// ---------------- f32x2 packed helpers (carrier: u64 -> .b64 regs) ----------
// Only fma.rn.f32x2 exists; all operands must be REGISTERS (no immediates).
//   add2(a,b) = a*ONE + b   (exact)
//   mul2(a,b) = a*b + ZERO  (same rounding as mul)
__device__ __forceinline__ u64 ffma2(u64 a, u64 b, u64 c) {
  u64 r;
  asm("fma.rn.f32x2 %0, %1, %2, %3;" : "=l"(r) : "l"(a), "l"(b), "l"(c));
  return r;
}
__device__ __forceinline__ u64 bcast2(float w) {
  u64 r;
  asm("mov.b64 %0, {%1, %1};" : "=l"(r) : "f"(w));
  return r;
}
__device__ __forceinline__ u64 fadd2(u64 a, u64 b) {
  return ffma2(a, bcast2(1.0f), b);
}
__device__ __forceinline__ u64 fmul2(u64 a, u64 b) {
  return ffma2(a, b, bcast2(0.0f));
}
__device__ __forceinline__ float2 unpack2(u64 v) {
  float2 f;
  asm("mov.b64 {%0, %1}, %2;" : "=f"(f.x), "=f"(f.y) : "l"(v));
  return f;
}

__device__ __forceinline__ void cp_async16(void* smem, const void* gmem) {
  unsigned s = (unsigned)__cvta_generic_to_shared(smem);
  asm volatile("cp.async.cg.shared.global [%0], [%1], 16;\n" ::"r"(s), "l"(gmem));
}
__device__ __forceinline__ void cp_commit() {
  asm volatile("cp.async.commit_group;\n");
}
__device__ __forceinline__ void cp_wait1() {
  asm volatile("cp.async.wait_group 1;\n");
}

__device__ __forceinline__ u64 warp_sum2(u64 v) {
  v = fadd2(v, __shfl_xor_sync(FULL_MASK, v, 16));
  v = fadd2(v, __shfl_xor_sync(FULL_MASK, v, 8));
  v = fadd2(v, __shfl_xor_sync(FULL_MASK, v, 4));
  v = fadd2(v, __shfl_xor_sync(FULL_MASK, v, 2));
  v = fadd2(v, __shfl_xor_sync(FULL_MASK, v, 1));
  return v;
}

// Cooperative load of one KT x HID weight tile into smem via cp.async.
__device__ __forceinline__ void load_tile(float* dst, const float* W, int k0,
                                          int tid) {
  const float4* src = reinterpret_cast<const float4*>(W + (size_t)k0 * HID);
  float4* d = reinterpret_cast<float4*>(dst);
  #pragma unroll
  for (int r = 0; r < TILE_F / 4 / NT; r++)  // 4 per thread
    cp_async16(&d[tid + r * NT], &src[tid + r * NT]);
}

// Stream NTILES weight tiles through a 3-buffer ring; one barrier per tile.
template <int NTILES, typename F>
__device__ __forceinline__ void stream_tiles(const float* __restrict__ W,
                                             float* wbuf, int tid, F&& consume) {
  load_tile(wbuf + 0 * TILE_F, W, 0 * KT, tid);
  cp_commit();
  load_tile(wbuf + 1 * TILE_F, W, 1 * KT, tid);
  cp_commit();
  #pragma unroll 1
  for (int tt = 0; tt < NTILES; tt++) {
    cp_wait1();          // tile tt complete (tt+1 may still be in flight)
    __syncthreads();     // everyone done with buffer (tt+2)%3 from iter tt-1
    if (tt + 2 < NTILES)
      load_tile(wbuf + ((tt + 2) % 3) * TILE_F, W, (tt + 2) * KT, tid);
    cp_commit();
    consume(wbuf + (tt % 3) * TILE_F, tt * KT);
  }
  __syncthreads();
}

// ------------------------------------------------------------------
// Process GG samples (slots sbase..sbase+GG-1 of d_perm), NR row-slots each.
// hT layout: hT[k*ROWS + g*NR + i] (feature-major, rows inner, pair-packed).
// ------------------------------------------------------------------
template <int GG, int NR>
__device__ __forceinline__ void run(const Params& P, float* sm, int sbase,
                                    int tid) {
  constexpr int ROWS = GG * NR;
  constexpr int NP   = NR / 2;            // packed row-pairs per sample
  float* hT    = sm;                       // HID*ROWS
  float* wbuf  = hT + HID * ROWS;          // 3*TILE_F
  float* msgs  = wbuf + 3 * TILE_F;        // GG*HID
  float* nfs   = msgs + GG * HID;          // GG*320
  float* red   = nfs + GG * NOBJ * NFD;    // GG*NR*16 floats
  float* stats = red + GG * NR * 16;       // GG*NR*2

  u64* red2  = reinterpret_cast<u64*>(red);   // pair sums
  u64* red2q = red2 + GG * NP * 8;            // pair sumsq

  const int lane = tid & 31, warp = tid >> 5, j = tid;

  int sid[GG]; int ncv[GG]; float invd[GG]; bool wok[GG];
  #pragma unroll
  for (int g = 0; g < GG; g++) {
    const int s = sbase + g;
    wok[g] = (s < P.B);
    sid[g] = wok[g] ? d_perm[s] : 0;
    int nc = wok[g] ? P.nn_c[sid[g]] : 0;
    ncv[g] = min(max(nc, 0), NOBJ);
    invd[g] = 1.0f / (float)(ncv[g] > 0 ? ncv[g] : 1);
  }

  // node features (GG*320 floats = GG*80 float4)
  for (int idx = tid; idx < GG * 80; idx += NT) {
    const int g = idx / 80, o = idx % 80;
    reinterpret_cast<float4*>(nfs)[idx] =
        reinterpret_cast<const float4*>(P.nf + (size_t)sid[g] * (NOBJ * NFD))[o];
  }
  __syncthreads();

  // ---------- node embed ----------
  {
    float wv[NFD];
    #pragma unroll
    for (int k = 0; k < NFD; k++) wv[k] = P.neW[k * HID + j];
    const float bias = P.neb[j];
    #pragma unroll
    for (int g = 0; g < GG; g++) {
      float ms = 0.f;
      #pragma unroll
      for (int i = 0; i < NR; i++) {
        const float4* rp = reinterpret_cast<const float4*>(nfs + g * 320 + i * NFD);
        float4 r0 = rp[0], r1 = rp[1], r2 = rp[2], r3 = rp[3];
        float a = bias;
        a = fmaf(r0.x, wv[0], a);  a = fmaf(r0.y, wv[1], a);
        a = fmaf(r0.z, wv[2], a);  a = fmaf(r0.w, wv[3], a);
        a = fmaf(r1.x, wv[4], a);  a = fmaf(r1.y, wv[5], a);
        a = fmaf(r1.z, wv[6], a);  a = fmaf(r1.w, wv[7], a);
        a = fmaf(r2.x, wv[8], a);  a = fmaf(r2.y, wv[9], a);
        a = fmaf(r2.z, wv[10], a); a = fmaf(r2.w, wv[11], a);
        a = fmaf(r3.x, wv[12], a); a = fmaf(r3.y, wv[13], a);
        a = fmaf(r3.z, wv[14], a); a = fmaf(r3.w, wv[15], a);
        hT[(size_t)j * ROWS + g * NR + i] = a;
        if (i < ncv[g]) ms += a;
      }
      msgs[g * HID + j] = ms * invd[g];
    }
  }
  __syncthreads();

  // ---------- two message-passing layers ----------
  #pragma unroll 1
  for (int L = 0; L < 2; L++) {
    const float* W1 = L ? P.g2W1 : P.g1W1;  const float* b1 = L ? P.g2b1 : P.g1b1;
    const float* W2 = L ? P.g2W2 : P.g1W2;  const float* b2 = L ? P.g2b2 : P.g1b2;
    const float* lg = L ? P.n2g  : P.n1g;   const float* lb = L ? P.n2b  : P.n1b;

    // ---- t = relu([h | msg] @ W1 + b1) ----
    u64 t2[GG][NP];
    float mac[GG];
    #pragma unroll
    for (int g = 0; g < GG; g++) {
      mac[g] = 0.f;
      #pragma unroll
      for (int p = 0; p < NP; p++) t2[g][p] = 0ull;
    }
    stream_tiles<512 / KT>(W1, wbuf, tid, [&](const float* wb, int k0) {
      if (k0 < HID) {
        #pragma unroll 4
        for (int kk = 0; kk < KT; kk++) {
          const u64 wd = bcast2(wb[kk * HID + j]);
          const ulonglong2* hv =
              reinterpret_cast<const ulonglong2*>(hT + (size_t)(k0 + kk) * ROWS);
          #pragma unroll
          for (int g = 0; g < GG; g++) {
            #pragma unroll
            for (int r = 0; r < NR / 4; r++) {
              ulonglong2 v = hv[g * (NR / 4) + r];
              t2[g][2 * r + 0] = ffma2(v.x, wd, t2[g][2 * r + 0]);
              t2[g][2 * r + 1] = ffma2(v.y, wd, t2[g][2 * r + 1]);
            }
          }
        }
      } else {
        #pragma unroll 8
        for (int kk = 0; kk < KT; kk++) {
          const float w = wb[kk * HID + j];
          const int km = k0 + kk - HID;
          #pragma unroll
          for (int g = 0; g < GG; g++)
            mac[g] = fmaf(msgs[g * HID + km], w, mac[g]);
        }
      }
    });

    // residual init (row-local) then overwrite hT with relu(t + mac + b1)
    u64 hn2[GG][NP];
    {
      const u64 b2d = bcast2(b2[j]);
      const float b1j = b1[j];
      #pragma unroll
      for (int g = 0; g < GG; g++) {
        const float m = mac[g] + b1j;
        #pragma unroll
        for (int p = 0; p < NP; p++) {
          u64* hp = reinterpret_cast<u64*>(hT + (size_t)j * ROWS + g * NR) + p;
          hn2[g][p] = fadd2(*hp, b2d);
          float2 u = unpack2(t2[g][p]);
          float2 o;
          o.x = fmaxf(u.x + m, 0.f);
          o.y = fmaxf(u.y + m, 0.f);
          *reinterpret_cast<float2*>(hp) = o;
        }
      }
    }
    // (no sync needed: thread j only touched its own feature row; the first
    //  barrier inside the next stream_tiles orders hT for cross-thread reads)

    // ---- hn += t @ W2 ----
    stream_tiles<HID / KT>(W2, wbuf, tid, [&](const float* wb, int k0) {
      #pragma unroll 4
      for (int kk = 0; kk < KT; kk++) {
        const u64 wd = bcast2(wb[kk * HID + j]);
        const ulonglong2* tv =
            reinterpret_cast<const ulonglong2*>(hT + (size_t)(k0 + kk) * ROWS);
        #pragma unroll
        for (int g = 0; g < GG; g++) {
          #pragma unroll
          for (int r = 0; r < NR / 4; r++) {
            ulonglong2 v = tv[g * (NR / 4) + r];
            hn2[g][2 * r + 0] = ffma2(v.x, wd, hn2[g][2 * r + 0]);
            hn2[g][2 * r + 1] = ffma2(v.y, wd, hn2[g][2 * r + 1]);
          }
        }
      }
    });

    // ---- LayerNorm stats (packed row-pair reductions) ----
    #pragma unroll
    for (int g = 0; g < GG; g++) {
      #pragma unroll
      for (int p = 0; p < NP; p++) {
        u64 s = warp_sum2(hn2[g][p]);
        u64 q = warp_sum2(fmul2(hn2[g][p], hn2[g][p]));
        if (lane == 0) {
          red2 [(g * NP + p) * 8 + warp] = s;
          red2q[(g * NP + p) * 8 + warp] = q;
        }
      }
    }
    __syncthreads();
    if (tid < GG * NR) {
      const int g = tid / NR, i = tid % NR, p = i >> 1, h = i & 1;
      float s = 0.f, q = 0.f;
      #pragma unroll
      for (int w = 0; w < 8; w++) {
        float2 us = unpack2(red2 [(g * NP + p) * 8 + w]);
        float2 uq = unpack2(red2q[(g * NP + p) * 8 + w]);
        s += h ? us.y : us.x;
        q += h ? uq.y : uq.x;
      }
      const float mean = s * (1.0f / HID);
      const float var  = q * (1.0f / HID) - mean * mean;
      stats[tid * 2 + 0] = mean;
      stats[tid * 2 + 1] = rsqrtf(var + 1e-5f);
    }
    __syncthreads();

    // ---- normalize, mask, write back, new msg ----
    const float gw = lg[j], gb = lb[j];
    #pragma unroll
    for (int g = 0; g < GG; g++) {
      float ms = 0.f;
      #pragma unroll
      for (int p = 0; p < NP; p++) {
        float2 u = unpack2(hn2[g][p]);
        #pragma unroll
        for (int h = 0; h < 2; h++) {
          const int i = 2 * p + h;
          float v = 0.f;
          if (i < ncv[g]) {
            const float* st = stats + (g * NR + i) * 2;
            v = (((h ? u.y : u.x) - st[0]) * st[1]) * gw + gb;
          }
          hT[(size_t)j * ROWS + g * NR + i] = v;
          ms += v;
        }
      }
      msgs[g * HID + j] = ms * invd[g];
    }
    __syncthreads();
  }
  // msgs == per-sample g vector, hT == final h

  // ---------- q = g @ pqW + pqb ----------
  float qv[GG];
  {
    const float qb = P.pqb[j];
    #pragma unroll
    for (int g = 0; g < GG; g++) qv[g] = qb;
    stream_tiles<HID / KT>(P.pqW, wbuf, tid, [&](const float* wb, int k0) {
      #pragma unroll 8
      for (int kk = 0; kk < KT; kk++) {
        const float w = wb[kk * HID + j];
        #pragma unroll
        for (int g = 0; g < GG; g++)
          qv[g] = fmaf(msgs[g * HID + k0 + kk], w, qv[g]);
      }
    });
  }

  // ---------- k = h @ pkW + pkb ; pl = q . k ----------
  u64 kq2[GG][NP];
  {
    const u64 pbd = bcast2(P.pkb[j]);
    #pragma unroll
    for (int g = 0; g < GG; g++)
      #pragma unroll
      for (int p = 0; p < NP; p++) kq2[g][p] = pbd;
    stream_tiles<HID / KT>(P.pkW, wbuf, tid, [&](const float* wb, int k0) {
      #pragma unroll 4
      for (int kk = 0; kk < KT; kk++) {
        const u64 wd = bcast2(wb[kk * HID + j]);
        const ulonglong2* hv =
            reinterpret_cast<const ulonglong2*>(hT + (size_t)(k0 + kk) * ROWS);
        #pragma unroll
        for (int g = 0; g < GG; g++) {
          #pragma unroll
          for (int r = 0; r < NR / 4; r++) {
            ulonglong2 v = hv[g * (NR / 4) + r];
            kq2[g][2 * r + 0] = ffma2(v.x, wd, kq2[g][2 * r + 0]);
            kq2[g][2 * r + 1] = ffma2(v.y, wd, kq2[g][2 * r + 1]);
          }
        }
      }
    });
  }
  #pragma unroll
  for (int g = 0; g < GG; g++) {
    #pragma unroll
    for (int p = 0; p < NP; p++) {
      u64 s = warp_sum2(fmul2(kq2[g][p], bcast2(qv[g])));
      if (lane == 0) red2[(g * NP + p) * 8 + warp] = s;
    }
  }
  __syncthreads();

  // ---------- pl output (all 20 slots; masked -> -1e9) ----------
  if (tid < GG * NOBJ) {
    const int g = tid / NOBJ, i = tid % NOBJ;
    if (wok[g]) {
      float v = -1e9f;
      if (i < ncv[g]) {
        const int p = i >> 1, h = i & 1;
        float s = 0.f;
        #pragma unroll
        for (int w = 0; w < 8; w++) {
          float2 u = unpack2(red2[(g * NP + p) * 8 + w]);
          s += h ? u.y : u.x;
        }
        v = s;
      }
      P.out[(size_t)P.B * 28 + (size_t)sid[g] * NOBJ + i] = v;
    }
  }

  // ---------- small heads from g-vector ----------
  if (tid < GG * 28) {
    const int g = tid / 28;
    int cc = tid % 28;
    if (wok[g]) {
      const float* W; float bb; float* o; int no;
      if (cc < 8)       { W = P.ohW;  bb = P.ohb[cc];      no = 8;
                          o = P.out + (size_t)sid[g] * 8 + cc; }
      else if (cc < 18) { cc -= 8;  W = P.c1W; bb = P.c1b[cc]; no = 10;
                          o = P.out + (size_t)P.B * 8 + (size_t)sid[g] * 10 + cc; }
      else              { cc -= 18; W = P.c2W; bb = P.c2b[cc]; no = 10;
                          o = P.out + (size_t)P.B * 18 + (size_t)sid[g] * 10 + cc; }
      float a0 = bb, a1 = 0.f, a2 = 0.f, a3 = 0.f;
      const float* mg = msgs + g * HID;
      #pragma unroll 2
      for (int k = 0; k < HID; k += 4) {
        a0 = fmaf(mg[k + 0], W[(k + 0) * no + cc], a0);
        a1 = fmaf(mg[k + 1], W[(k + 1) * no + cc], a1);
        a2 = fmaf(mg[k + 2], W[(k + 2) * no + cc], a2);
        a3 = fmaf(mg[k + 3], W[(k + 3) * no + cc], a3);
      }
      *o = (a0 + a1) + (a2 + a3);
    }
  }
}

__global__ void __launch_bounds__(1024, 1) pack_kernel(const int* __restrict__ nn_c, int B) {
  __shared__ int cnt[5], base[5];
  const int tid = threadIdx.x;
  if (tid < 5) cnt[tid] = 0;
  __syncthreads();
  for (int i = tid; i < B; i += 1024) {
    int nc = min(max(nn_c[i], 0), NOBJ);
    int g = ((nc > 0 ? nc : 1) + 3) >> 2;  // 1..5
    atomicAdd(&cnt[g - 1], 1);
  }
  __syncthreads();
  if (tid == 0) {
    int s = 0;
    for (int g = 0; g < 5; g++) { base[g] = s; s += cnt[g]; }
  }
  __syncthreads();
  if (tid < 5) cnt[tid] = 0;
  __syncthreads();
  for (int i = tid; i < B; i += 1024) {
    int nc = min(max(nn_c[i], 0), NOBJ);
    int g = ((nc > 0 ? nc : 1) + 3) >> 2;
    int slot = base[g - 1] + atomicAdd(&cnt[g - 1], 1);
    d_perm[slot] = i;
  }
}

__global__ void __launch_bounds__(NT, 2) gnn_kernel(Params P) {
  extern __shared__ __align__(16) float sm[];
  const int c = blockIdx.x;
  int gmax = 1;
  #pragma unroll
  for (int g = 0; g < 4; g++) {
    const int s = c * 4 + g;
    if (s < P.B) {
      int nc = min(max(P.nn_c[d_perm[s]], 0), NOBJ);
      int gg = ((nc > 0 ? nc : 1) + 3) >> 2;
      gmax = max(gmax, gg);
    }
  }
  const int tid = threadIdx.x;
  switch (gmax) {
    case 1: run<4, 4>(P, sm, c * 4, tid); break;
    case 2: run<4, 8>(P, sm, c * 4, tid); break;
    case 3:
      run<2, 12>(P, sm, c * 4, tid); __syncthreads();
      run<2, 12>(P, sm, c * 4 + 2, tid); break;
    case 4:
      run<2, 16>(P, sm, c * 4, tid); __syncthreads();
      run<2, 16>(P, sm, c * 4 + 2, tid); break;
    default:
      run<2, 20>(P, sm, c * 4, tid); __syncthreads();
      run<2, 20>(P, sm, c * 4 + 2, tid); break;
  }
}

// smem size = max over variants; (GG=2,NR=20) is the largest:
constexpr int SMEM_FLOATS =
    HID * (2 * 20) + 3 * TILE_F + 2 * HID + 2 * NOBJ * NFD + 2 * 20 * 16 + 2 * 20 * 2;
constexpr int SMEM_BYTES = SMEM_FLOATS * 4;  // 97,600 B -> 2 CTAs/SM

}  // namespace

extern "C" void kernel_launch(void* const* d_in, const int* in_sizes, int n_in,
                              void* d_out, int out_size) {
  Params P;
  P.nf   = (const float*)d_in[0];
  P.nn_c = (const int*)d_in[1];
  P.neW  = (const float*)d_in[2];  P.neb  = (const float*)d_in[3];
  P.g1W1 = (const float*)d_in[4];  P.g1b1 = (const float*)d_in[5];
  P.g1W2 = (const float*)d_in[6];  P.g1b2 = (const float*)d_in[7];
  P.g2W1 = (const float*)d_in[8];  P.g2b1 = (const float*)d_in[9];
  P.g2W2 = (const float*)d_in[10]; P.g2b2 = (const float*)d_in[11];
  P.n1g  = (const float*)d_in[12]; P.n1b  = (const float*)d_in[13];
  P.n2g  = (const float*)d_in[14]; P.n2b  = (const float*)d_in[15];
  P.ohW  = (const float*)d_in[16]; P.ohb  = (const float*)d_in[17];
  P.c1W  = (const float*)d_in[18]; P.c1b  = (const float*)d_in[19];
  P.c2W  = (const float*)d_in[20]; P.c2b  = (const float*)d_in[21];
  P.pqW  = (const float*)d_in[22]; P.pqb  = (const float*)d_in[23];
  P.pkW  = (const float*)d_in[24]; P.pkb  = (const float*)d_in[25];
  P.out  = (float*)d_out;
  P.B    = in_sizes[1];

  cudaFuncSetAttribute(gnn_kernel, cudaFuncAttributeMaxDynamicSharedMemorySize,
                       SMEM_BYTES);

  pack_kernel<<<1, 1024>>>(P.nn_c, P.B);
  const int nblocks = (P.B + 3) / 4;
  gnn_kernel<<<nblocks, NT, SMEM_BYTES>>>(P);
}

// round 6
// speedup vs baseline: 1.6447x; 1.3105x over previous
#include <cuda_runtime.h>

namespace {

constexpr int HID  = 256;
constexpr int NOBJ = 20;
constexpr int NFD  = 16;
constexpr int NT   = 256;        // threads per block
constexpr int KT   = 16;         // weight k-tile rows
constexpr int TILE_F = KT * HID; // floats per weight tile (4096)
constexpr int MAXB = 16384;
constexpr unsigned FULL_MASK = 0xFFFFFFFFu;

using u64 = unsigned long long;

__device__ int d_perm[MAXB];

struct Params {
  const float* __restrict__ nf;   const int* __restrict__ nn_c;
  const float* __restrict__ neW;  const float* __restrict__ neb;
  const float* __restrict__ g1W1; const float* __restrict__ g1b1;
  const float* __restrict__ g1W2; const float* __restrict__ g1b2;
  const float* __restrict__ g2W1; const float* __restrict__ g2b1;
  const float* __restrict__ g2W2; const float* __restrict__ g2b2;
  const float* __restrict__ n1g;  const float* __restrict__ n1b;
  const float* __restrict__ n2g;  const float* __restrict__ n2b;
  const float* __restrict__ ohW;  const float* __restrict__ ohb;
  const float* __restrict__ c1W;  const float* __restrict__ c1b;
  const float* __restrict__ c2W;  const float* __restrict__ c2b;
  const float* __restrict__ pqW;  const float* __restrict__ pqb;
  const float* __restrict__ pkW;  const float* __restrict__ pkb;
  float* __restrict__ out;
  int B;
};

// ---------------- f32x2 packed helpers (carrier: u64, register-only) --------
__device__ __forceinline__ u64 ffma2(u64 a, u64 b, u64 c) {
  u64 r;
  asm("fma.rn.f32x2 %0, %1, %2, %3;" : "=l"(r) : "l"(a), "l"(b), "l"(c));
  return r;
}
__device__ __forceinline__ u64 bcast2(float w) {
  u64 r;
  asm("mov.b64 %0, {%1, %1};" : "=l"(r) : "f"(w));
  return r;
}
__device__ __forceinline__ u64 fadd2(u64 a, u64 b) { return ffma2(a, bcast2(1.0f), b); }
__device__ __forceinline__ u64 fmul2(u64 a, u64 b) { return ffma2(a, b, bcast2(0.0f)); }
__device__ __forceinline__ float2 unpack2(u64 v) {
  float2 f;
  asm("mov.b64 {%0, %1}, %2;" : "=f"(f.x), "=f"(f.y) : "l"(v));
  return f;
}

__device__ __forceinline__ void cp_async16(void* smem, const void* gmem) {
  unsigned s = (unsigned)__cvta_generic_to_shared(smem);
  asm volatile("cp.async.cg.shared.global [%0], [%1], 16;\n" ::"r"(s), "l"(gmem));
}
__device__ __forceinline__ void cp_commit() { asm volatile("cp.async.commit_group;\n"); }
__device__ __forceinline__ void cp_wait1()  { asm volatile("cp.async.wait_group 1;\n"); }

// Cooperative load of one KT x HID weight tile into smem via cp.async.
__device__ __forceinline__ void load_tile(float* dst, const float* W, int k0, int tid) {
  const float4* src = reinterpret_cast<const float4*>(W + (size_t)k0 * HID);
  float4* d = reinterpret_cast<float4*>(dst);
  #pragma unroll
  for (int r = 0; r < TILE_F / 4 / NT; r++)
    cp_async16(&d[tid + r * NT], &src[tid + r * NT]);
}

// Stream NTILES weight tiles through a 3-buffer ring; one barrier per tile.
template <int NTILES, typename F>
__device__ __forceinline__ void stream_tiles(const float* __restrict__ W,
                                             float* wbuf, int tid, F&& consume) {
  load_tile(wbuf + 0 * TILE_F, W, 0 * KT, tid);
  cp_commit();
  load_tile(wbuf + 1 * TILE_F, W, 1 * KT, tid);
  cp_commit();
  #pragma unroll 1
  for (int tt = 0; tt < NTILES; tt++) {
    cp_wait1();
    __syncthreads();
    if (tt + 2 < NTILES)
      load_tile(wbuf + ((tt + 2) % 3) * TILE_F, W, (tt + 2) * KT, tid);
    cp_commit();
    consume(wbuf + (tt % 3) * TILE_F, tt * KT);
  }
  __syncthreads();
}

// Load NPG packed row-pairs (u64s) from a 16B-aligned group base.
template <int NPG>
__device__ __forceinline__ void ld_grp(u64* d, const float* p) {
  const u64* q = reinterpret_cast<const u64*>(p);
  #pragma unroll
  for (int i = 0; i + 2 <= NPG; i += 2) {
    ulonglong2 v = *reinterpret_cast<const ulonglong2*>(q + i);
    d[i] = v.x; d[i + 1] = v.y;
  }
  if constexpr (NPG & 1) d[NPG - 1] = q[NPG - 1];
}

// One KT-deep MMA tile: thread accumulates 4 cols x NPG row-pairs.
template <int NPG, int KSTR_F>
__device__ __forceinline__ void mma_tile(const float* __restrict__ wb,
                                         const float* __restrict__ hsrc,
                                         int c0, u64 (&acc)[4][NPG]) {
  #pragma unroll 4
  for (int kk = 0; kk < KT; kk++) {
    const float4 wf = *reinterpret_cast<const float4*>(wb + kk * HID + c0);
    u64 h[NPG];
    ld_grp<NPG>(h, hsrc + kk * KSTR_F);
    const u64 w0 = bcast2(wf.x), w1 = bcast2(wf.y);
    const u64 w2 = bcast2(wf.z), w3 = bcast2(wf.w);
    #pragma unroll
    for (int p = 0; p < NPG; p++) {
      acc[0][p] = ffma2(h[p], w0, acc[0][p]);
      acc[1][p] = ffma2(h[p], w1, acc[1][p]);
      acc[2][p] = ffma2(h[p], w2, acc[2][p]);
      acc[3][p] = ffma2(h[p], w3, acc[3][p]);
    }
  }
}

// ------------------------------------------------------------------
// 2 samples per CTA. hT layout per feature k: 4 row-groups (2 per sample),
// each NPG packed pairs, group stride GSTR_F floats (16B aligned).
// Thread (cg=tid>>2, rg=tid&3) owns cols [4cg,4cg+4) x rows of group rg.
// ------------------------------------------------------------------
template <int NR>
__device__ __forceinline__ void run(const Params& P, float* sm, int sbase, int tid) {
  constexpr int RPG = NR / 2;                         // rows per group
  constexpr int NPG = NR / 4;                         // pairs per group
  constexpr int GSTR_F = (((NPG * 8) + 15) & ~15) / 4; // group stride (floats)
  constexpr int KSTR_F = 4 * GSTR_F;                  // per-k stride (floats)

  float* hT   = sm;                       // HID * KSTR_F
  float* wbuf = hT + HID * KSTR_F;        // 3 * TILE_F
  float* msgs = wbuf + 3 * TILE_F;        // 2 * HID
  float* nfs  = msgs + 2 * HID;           // 2 * 320
  u64*  red   = reinterpret_cast<u64*>(nfs + 2 * NOBJ * NFD);  // [2][8][4][NPG]

  const int lane = tid & 31, warp = tid >> 5;
  const int cg = tid >> 2, rg = tid & 3, c0 = cg * 4, g = rg >> 1;

  int sid[2]; int ncv[2]; float invd[2]; bool wok[2];
  #pragma unroll
  for (int s = 0; s < 2; s++) {
    const int ss = sbase + s;
    wok[s] = (ss < P.B);
    sid[s] = wok[s] ? d_perm[ss] : 0;
    int nc = wok[s] ? P.nn_c[sid[s]] : 0;
    ncv[s] = min(max(nc, 0), NOBJ);
    invd[s] = 1.0f / (float)(ncv[s] > 0 ? ncv[s] : 1);
  }

  // node features (2*320 floats = 160 float4)
  for (int idx = tid; idx < 2 * 80; idx += NT) {
    const int s = idx / 80, o = idx % 80;
    reinterpret_cast<float4*>(nfs)[idx] =
        reinterpret_cast<const float4*>(P.nf + (size_t)sid[s] * (NOBJ * NFD))[o];
  }
  __syncthreads();

  // ---------- node embed (thread j = feature) ----------
  {
    const int j = tid;
    float wv[NFD];
    #pragma unroll
    for (int k = 0; k < NFD; k++) wv[k] = P.neW[k * HID + j];
    const float bias = P.neb[j];
    #pragma unroll
    for (int s = 0; s < 2; s++) {
      float ms = 0.f;
      #pragma unroll
      for (int i = 0; i < NR; i += 2) {
        float a2[2];
        #pragma unroll
        for (int t = 0; t < 2; t++) {
          const float4* rp = reinterpret_cast<const float4*>(nfs + s * 320 + (i + t) * NFD);
          float4 r0 = rp[0], r1 = rp[1], r2 = rp[2], r3 = rp[3];
          float a = bias;
          a = fmaf(r0.x, wv[0], a);  a = fmaf(r0.y, wv[1], a);
          a = fmaf(r0.z, wv[2], a);  a = fmaf(r0.w, wv[3], a);
          a = fmaf(r1.x, wv[4], a);  a = fmaf(r1.y, wv[5], a);
          a = fmaf(r1.z, wv[6], a);  a = fmaf(r1.w, wv[7], a);
          a = fmaf(r2.x, wv[8], a);  a = fmaf(r2.y, wv[9], a);
          a = fmaf(r2.z, wv[10], a); a = fmaf(r2.w, wv[11], a);
          a = fmaf(r3.x, wv[12], a); a = fmaf(r3.y, wv[13], a);
          a = fmaf(r3.z, wv[14], a); a = fmaf(r3.w, wv[15], a);
          a2[t] = a;
          if (i + t < ncv[s]) ms += a;
        }
        const int grp = s * 2 + i / RPG;
        const int slot = i % RPG;
        *reinterpret_cast<float2*>(hT + (size_t)j * KSTR_F + grp * GSTR_F + slot) =
            make_float2(a2[0], a2[1]);
      }
      msgs[s * HID + j] = ms * invd[s];
    }
  }
  __syncthreads();

  // ---------- two message-passing layers ----------
  #pragma unroll 1
  for (int L = 0; L < 2; L++) {
    const float* W1 = L ? P.g2W1 : P.g1W1;  const float* b1 = L ? P.g2b1 : P.g1b1;
    const float* W2 = L ? P.g2W2 : P.g1W2;  const float* b2 = L ? P.g2b2 : P.g1b2;
    const float* lg = L ? P.n2g  : P.n1g;   const float* lb = L ? P.n2b  : P.n1b;

    // ---- t = relu([h | msg] @ W1 + b1) ----
    u64 t2[4][NPG];
    float mac[4];
    #pragma unroll
    for (int c = 0; c < 4; c++) {
      mac[c] = 0.f;
      #pragma unroll
      for (int p = 0; p < NPG; p++) t2[c][p] = 0ull;
    }
    stream_tiles<512 / KT>(W1, wbuf, tid, [&](const float* wb, int k0) {
      if (k0 < HID) {
        mma_tile<NPG, KSTR_F>(wb, hT + (size_t)k0 * KSTR_F + rg * GSTR_F, c0, t2);
      } else {
        #pragma unroll 4
        for (int kk = 0; kk < KT; kk++) {
          const float4 wf = *reinterpret_cast<const float4*>(wb + kk * HID + c0);
          const float m = msgs[g * HID + k0 + kk - HID];
          mac[0] = fmaf(m, wf.x, mac[0]); mac[1] = fmaf(m, wf.y, mac[1]);
          mac[2] = fmaf(m, wf.z, mac[2]); mac[3] = fmaf(m, wf.w, mac[3]);
        }
      }
    });

    // ---- epilogue 1: acc2 = h_old + b2 (residual pre-add); hT <- relu(t) ----
    u64 acc2[4][NPG];
    {
      const float4 b1v = *reinterpret_cast<const float4*>(b1 + c0);
      const float4 b2v = *reinterpret_cast<const float4*>(b2 + c0);
      const float b1a[4] = {b1v.x, b1v.y, b1v.z, b1v.w};
      const float b2a[4] = {b2v.x, b2v.y, b2v.z, b2v.w};
      #pragma unroll
      for (int c = 0; c < 4; c++) {
        float* hcol = hT + (size_t)(c0 + c) * KSTR_F + rg * GSTR_F;
        u64 hold[NPG];
        ld_grp<NPG>(hold, hcol);
        const u64 b2d = bcast2(b2a[c]);
        #pragma unroll
        for (int p = 0; p < NPG; p++) acc2[c][p] = fadd2(hold[p], b2d);
        const float m = mac[c] + b1a[c];
        #pragma unroll
        for (int p = 0; p < NPG; p++) {
          float2 u = unpack2(t2[c][p]);
          *reinterpret_cast<float2*>(hcol + 2 * p) =
              make_float2(fmaxf(u.x + m, 0.f), fmaxf(u.y + m, 0.f));
        }
      }
    }
    __syncthreads();

    // ---- acc2 += t @ W2  (hn = h_old + b2 + t@W2) ----
    stream_tiles<HID / KT>(W2, wbuf, tid, [&](const float* wb, int k0) {
      mma_tile<NPG, KSTR_F>(wb, hT + (size_t)k0 * KSTR_F + rg * GSTR_F, c0, acc2);
    });

    // ---- LayerNorm stats (reduce over 256 features) ----
    u64 s2[NPG], q2[NPG];
    #pragma unroll
    for (int p = 0; p < NPG; p++) {
      u64 s = fadd2(fadd2(acc2[0][p], acc2[1][p]), fadd2(acc2[2][p], acc2[3][p]));
      u64 q = fmul2(acc2[0][p], acc2[0][p]);
      q = ffma2(acc2[1][p], acc2[1][p], q);
      q = ffma2(acc2[2][p], acc2[2][p], q);
      q = ffma2(acc2[3][p], acc2[3][p], q);
      s2[p] = s; q2[p] = q;
    }
    #pragma unroll
    for (int off = 4; off <= 16; off <<= 1) {
      #pragma unroll
      for (int p = 0; p < NPG; p++) {
        s2[p] = fadd2(s2[p], __shfl_xor_sync(FULL_MASK, s2[p], off));
        q2[p] = fadd2(q2[p], __shfl_xor_sync(FULL_MASK, q2[p], off));
      }
    }
    if ((lane >> 2) == 0) {
      #pragma unroll
      for (int p = 0; p < NPG; p++) {
        red[((0 * 8 + warp) * 4 + rg) * NPG + p] = s2[p];
        red[((1 * 8 + warp) * 4 + rg) * NPG + p] = q2[p];
      }
    }
    __syncthreads();

    float2 mean2[NPG], rstd2[NPG];
    #pragma unroll
    for (int p = 0; p < NPG; p++) {
      u64 S = red[((0 * 8 + 0) * 4 + rg) * NPG + p];
      u64 Q = red[((1 * 8 + 0) * 4 + rg) * NPG + p];
      #pragma unroll
      for (int w = 1; w < 8; w++) {
        S = fadd2(S, red[((0 * 8 + w) * 4 + rg) * NPG + p]);
        Q = fadd2(Q, red[((1 * 8 + w) * 4 + rg) * NPG + p]);
      }
      float2 su = unpack2(S), qu = unpack2(Q);
      const float mx = su.x * (1.0f / HID), my = su.y * (1.0f / HID);
      mean2[p] = make_float2(mx, my);
      rstd2[p] = make_float2(rsqrtf(qu.x * (1.0f / HID) - mx * mx + 1e-5f),
                             rsqrtf(qu.y * (1.0f / HID) - my * my + 1e-5f));
    }

    // ---- normalize, mask, write back, new msg ----
    const float4 lgv = *reinterpret_cast<const float4*>(lg + c0);
    const float4 lbv = *reinterpret_cast<const float4*>(lb + c0);
    const float lga[4] = {lgv.x, lgv.y, lgv.z, lgv.w};
    const float lba[4] = {lbv.x, lbv.y, lbv.z, lbv.w};
    float msum[4] = {0.f, 0.f, 0.f, 0.f};
    const int rbase = (rg & 1) * RPG;
    #pragma unroll
    for (int c = 0; c < 4; c++) {
      float* hcol = hT + (size_t)(c0 + c) * KSTR_F + rg * GSTR_F;
      #pragma unroll
      for (int p = 0; p < NPG; p++) {
        float2 u = unpack2(acc2[c][p]);
        float v0 = 0.f, v1 = 0.f;
        if (rbase + 2 * p     < ncv[g]) v0 = (u.x - mean2[p].x) * rstd2[p].x * lga[c] + lba[c];
        if (rbase + 2 * p + 1 < ncv[g]) v1 = (u.y - mean2[p].y) * rstd2[p].y * lga[c] + lba[c];
        *reinterpret_cast<float2*>(hcol + 2 * p) = make_float2(v0, v1);
        msum[c] += v0 + v1;
      }
    }
    #pragma unroll
    for (int c = 0; c < 4; c++)
      msum[c] += __shfl_xor_sync(FULL_MASK, msum[c], 1);
    if ((rg & 1) == 0) {
      *reinterpret_cast<float4*>(msgs + g * HID + c0) =
          make_float4(msum[0] * invd[g], msum[1] * invd[g],
                      msum[2] * invd[g], msum[3] * invd[g]);
    }
    __syncthreads();
  }
  // msgs == per-sample g vector, hT == final h

  // ---------- q = g @ pqW + pqb ----------
  float qv[4];
  {
    const float4 qb = *reinterpret_cast<const float4*>(P.pqb + c0);
    qv[0] = qb.x; qv[1] = qb.y; qv[2] = qb.z; qv[3] = qb.w;
  }
  stream_tiles<HID / KT>(P.pqW, wbuf, tid, [&](const float* wb, int k0) {
    #pragma unroll 4
    for (int kk = 0; kk < KT; kk++) {
      const float4 wf = *reinterpret_cast<const float4*>(wb + kk * HID + c0);
      const float m = msgs[g * HID + k0 + kk];
      qv[0] = fmaf(m, wf.x, qv[0]); qv[1] = fmaf(m, wf.y, qv[1]);
      qv[2] = fmaf(m, wf.z, qv[2]); qv[3] = fmaf(m, wf.w, qv[3]);
    }
  });

  // ---------- k = h @ pkW + pkb ; pl = q . k ----------
  u64 ka[4][NPG];
  {
    const float4 pb = *reinterpret_cast<const float4*>(P.pkb + c0);
    const float pba[4] = {pb.x, pb.y, pb.z, pb.w};
    #pragma unroll
    for (int c = 0; c < 4; c++) {
      const u64 d = bcast2(pba[c]);
      #pragma unroll
      for (int p = 0; p < NPG; p++) ka[c][p] = d;
    }
  }
  stream_tiles<HID / KT>(P.pkW, wbuf, tid, [&](const float* wb, int k0) {
    mma_tile<NPG, KSTR_F>(wb, hT + (size_t)k0 * KSTR_F + rg * GSTR_F, c0, ka);
  });
  {
    u64 part[NPG];
    const u64 q0 = bcast2(qv[0]), q1 = bcast2(qv[1]);
    const u64 q2d = bcast2(qv[2]), q3 = bcast2(qv[3]);
    #pragma unroll
    for (int p = 0; p < NPG; p++) {
      u64 s = fmul2(ka[0][p], q0);
      s = ffma2(ka[1][p], q1, s);
      s = ffma2(ka[2][p], q2d, s);
      s = ffma2(ka[3][p], q3, s);
      part[p] = s;
    }
    #pragma unroll
    for (int off = 4; off <= 16; off <<= 1)
      #pragma unroll
      for (int p = 0; p < NPG; p++)
        part[p] = fadd2(part[p], __shfl_xor_sync(FULL_MASK, part[p], off));
    if ((lane >> 2) == 0) {
      #pragma unroll
      for (int p = 0; p < NPG; p++)
        red[((0 * 8 + warp) * 4 + rg) * NPG + p] = part[p];
    }
  }
  __syncthreads();

  // ---------- pl output (all 20 slots; masked -> -1e9) ----------
  if (tid < 2 * NOBJ) {
    const int s = tid / NOBJ, i = tid % NOBJ;
    if (wok[s]) {
      float v = -1e9f;
      if (i < ncv[s]) {
        const int grp = s * 2 + i / RPG;
        const int slot = i % RPG;
        const int p = slot >> 1, hh = slot & 1;
        u64 S = red[((0 * 8 + 0) * 4 + grp) * NPG + p];
        #pragma unroll
        for (int w = 1; w < 8; w++)
          S = fadd2(S, red[((0 * 8 + w) * 4 + grp) * NPG + p]);
        float2 u = unpack2(S);
        v = hh ? u.y : u.x;
      }
      P.out[(size_t)P.B * 28 + (size_t)sid[s] * NOBJ + i] = v;
    }
  }

  // ---------- small heads from g-vector ----------
  if (tid < 2 * 28) {
    const int s = tid / 28;
    int cc = tid % 28;
    if (wok[s]) {
      const float* W; float bb; float* o; int no;
      if (cc < 8)       { W = P.ohW;  bb = P.ohb[cc];      no = 8;
                          o = P.out + (size_t)sid[s] * 8 + cc; }
      else if (cc < 18) { cc -= 8;  W = P.c1W; bb = P.c1b[cc]; no = 10;
                          o = P.out + (size_t)P.B * 8 + (size_t)sid[s] * 10 + cc; }
      else              { cc -= 18; W = P.c2W; bb = P.c2b[cc]; no = 10;
                          o = P.out + (size_t)P.B * 18 + (size_t)sid[s] * 10 + cc; }
      float a0 = bb, a1 = 0.f, a2 = 0.f, a3 = 0.f;
      const float* mg = msgs + s * HID;
      #pragma unroll 2
      for (int k = 0; k < HID; k += 4) {
        a0 = fmaf(mg[k + 0], W[(k + 0) * no + cc], a0);
        a1 = fmaf(mg[k + 1], W[(k + 1) * no + cc], a1);
        a2 = fmaf(mg[k + 2], W[(k + 2) * no + cc], a2);
        a3 = fmaf(mg[k + 3], W[(k + 3) * no + cc], a3);
      }
      *o = (a0 + a1) + (a2 + a3);
    }
  }
}

__global__ void __launch_bounds__(1024, 1) pack_kernel(const int* __restrict__ nn_c, int B) {
  __shared__ int cnt[5], base[5];
  const int tid = threadIdx.x;
  if (tid < 5) cnt[tid] = 0;
  __syncthreads();
  for (int i = tid; i < B; i += 1024) {
    int nc = min(max(nn_c[i], 0), NOBJ);
    int g = ((nc > 0 ? nc : 1) + 3) >> 2;  // 1..5
    atomicAdd(&cnt[g - 1], 1);
  }
  __syncthreads();
  if (tid == 0) {
    int s = 0;
    for (int g = 0; g < 5; g++) { base[g] = s; s += cnt[g]; }
  }
  __syncthreads();
  if (tid < 5) cnt[tid] = 0;
  __syncthreads();
  for (int i = tid; i < B; i += 1024) {
    int nc = min(max(nn_c[i], 0), NOBJ);
    int g = ((nc > 0 ? nc : 1) + 3) >> 2;
    int slot = base[g - 1] + atomicAdd(&cnt[g - 1], 1);
    d_perm[slot] = i;
  }
}

__global__ void __launch_bounds__(NT, 2) gnn_kernel(Params P) {
  extern __shared__ __align__(16) float sm[];
  const int c = blockIdx.x;
  int gmax = 1;
  #pragma unroll
  for (int s = 0; s < 2; s++) {
    const int ss = c * 2 + s;
    if (ss < P.B) {
      int nc = min(max(P.nn_c[d_perm[ss]], 0), NOBJ);
      int gg = ((nc > 0 ? nc : 1) + 3) >> 2;
      gmax = max(gmax, gg);
    }
  }
  const int tid = threadIdx.x;
  switch (gmax) {
    case 1:  run<4>(P, sm, c * 2, tid);  break;
    case 2:  run<8>(P, sm, c * 2, tid);  break;
    case 3:  run<12>(P, sm, c * 2, tid); break;
    case 4:  run<16>(P, sm, c * 2, tid); break;
    default: run<20>(P, sm, c * 2, tid); break;
  }
}

// smem for the largest variant (NR=20): KSTR_F = 48 floats
constexpr int SMEM_FLOATS =
    HID * 48 + 3 * TILE_F + 2 * HID + 2 * NOBJ * NFD + (2 * 8 * 4 * 5) * 2;
constexpr int SMEM_BYTES = SMEM_FLOATS * 4;  // 105,472 B -> 2 CTAs/SM

}  // namespace

extern "C" void kernel_launch(void* const* d_in, const int* in_sizes, int n_in,
                              void* d_out, int out_size) {
  Params P;
  P.nf   = (const float*)d_in[0];
  P.nn_c = (const int*)d_in[1];
  P.neW  = (const float*)d_in[2];  P.neb  = (const float*)d_in[3];
  P.g1W1 = (const float*)d_in[4];  P.g1b1 = (const float*)d_in[5];
  P.g1W2 = (const float*)d_in[6];  P.g1b2 = (const float*)d_in[7];
  P.g2W1 = (const float*)d_in[8];  P.g2b1 = (const float*)d_in[9];
  P.g2W2 = (const float*)d_in[10]; P.g2b2 = (const float*)d_in[11];
  P.n1g  = (const float*)d_in[12]; P.n1b  = (const float*)d_in[13];
  P.n2g  = (const float*)d_in[14]; P.n2b  = (const float*)d_in[15];
  P.ohW  = (const float*)d_in[16]; P.ohb  = (const float*)d_in[17];
  P.c1W  = (const float*)d_in[18]; P.c1b  = (const float*)d_in[19];
  P.c2W  = (const float*)d_in[20]; P.c2b  = (const float*)d_in[21];
  P.pqW  = (const float*)d_in[22]; P.pqb  = (const float*)d_in[23];
  P.pkW  = (const float*)d_in[24]; P.pkb  = (const float*)d_in[25];
  P.out  = (float*)d_out;
  P.B    = in_sizes[1];

  cudaFuncSetAttribute(gnn_kernel, cudaFuncAttributeMaxDynamicSharedMemorySize,
                       SMEM_BYTES);

  pack_kernel<<<1, 1024>>>(P.nn_c, P.B);
  const int nblocks = (P.B + 1) / 2;
  gnn_kernel<<<nblocks, NT, SMEM_BYTES>>>(P);
}